// round 2
// baseline (speedup 1.0000x reference)
#include <cuda_runtime.h>

// Problem constants (fixed by reference setup_inputs)
#define C_    128
#define D_    24
#define H_    128
#define W_    128
#define HW_   (H_ * W_)
#define DHW_  (D_ * HW_)
#define OUTH  7
#define OUTD  4
#define SN_   2
#define NBINS (OUTD * OUTH * OUTH)   // 196
#define CG    16                     // channels per block (gridDim.y = C_/CG = 8)
#define NTAP  (SN_ * 2)              // 4 taps per axis (2 samples x 2 corners)

#define SCALE_XY 0.125f
#define SCALE_Z  0.25f

__global__ __launch_bounds__(NBINS, 5)
void roialign3d_kernel(const float* __restrict__ feat,
                       const float* __restrict__ rois,
                       float* __restrict__ out,
                       int R)
{
    const int r   = blockIdx.x;          // roi index
    const int cg  = blockIdx.y;          // channel group
    const int bin = threadIdx.x;         // 0..195  (output bin; contiguous out dim)
    const int w   = bin % OUTH;
    const int h   = (bin / OUTH) % OUTH;
    const int d   = bin / (OUTH * OUTH);

    // ---- ROI params (uniform across block) ----
    const float* roi = rois + (size_t)r * 7;
    const int   b  = (int)__ldg(roi + 0);
    const float x1 = __ldg(roi + 1) * SCALE_XY;
    const float y1 = __ldg(roi + 2) * SCALE_XY;
    const float x2 = __ldg(roi + 3) * SCALE_XY;
    const float y2 = __ldg(roi + 4) * SCALE_XY;
    const float z1 = __ldg(roi + 5) * SCALE_Z;
    const float z2 = __ldg(roi + 6) * SCALE_Z;

    const float bw = fmaxf(x2 - x1, 1.0f) * (1.0f / OUTH);
    const float bh = fmaxf(y2 - y1, 1.0f) * (1.0f / OUTH);
    const float bd = fmaxf(z2 - z1, 1.0f) * (1.0f / OUTD);

    // ---- Per-bin taps: 4 per axis = (2 samples) x (low, high corner) ----
    // Indices are always clipped in-bounds; validity and corner weights are
    // folded into the tap weight (f == 0 exactly whenever hi clips to lo, so
    // the duplicated-index tap matches the reference bit pattern).
    int   zoff[NTAP]; float zw[NTAP];
    int   yoff[NTAP]; float yw[NTAP];
    int   xoff[NTAP]; float xw[NTAP];

#pragma unroll
    for (int s = 0; s < SN_; s++) {
        // z axis (dim D_)
        {
            float c  = z1 + ((float)d + 0.25f + 0.5f * (float)s) * bd;
            float v  = (c > -1.0f && c < (float)D_) ? 1.0f : 0.0f;
            float cc = fminf(fmaxf(c, 0.0f), (float)(D_ - 1));
            int   lo = (int)cc;                      // floor, cc >= 0
            int   hi = (lo < D_ - 1) ? lo + 1 : lo;
            float f  = cc - (float)lo;
            zoff[2*s]   = lo * HW_;  zw[2*s]   = (1.0f - f) * v;
            zoff[2*s+1] = hi * HW_;  zw[2*s+1] = f * v;
        }
        // y axis (dim H_)
        {
            float c  = y1 + ((float)h + 0.25f + 0.5f * (float)s) * bh;
            float v  = (c > -1.0f && c < (float)H_) ? 1.0f : 0.0f;
            float cc = fminf(fmaxf(c, 0.0f), (float)(H_ - 1));
            int   lo = (int)cc;
            int   hi = (lo < H_ - 1) ? lo + 1 : lo;
            float f  = cc - (float)lo;
            yoff[2*s]   = lo * W_;   yw[2*s]   = (1.0f - f) * v;
            yoff[2*s+1] = hi * W_;   yw[2*s+1] = f * v;
        }
        // x axis (dim W_)
        {
            float c  = x1 + ((float)w + 0.25f + 0.5f * (float)s) * bw;
            float v  = (c > -1.0f && c < (float)W_) ? 1.0f : 0.0f;
            float cc = fminf(fmaxf(c, 0.0f), (float)(W_ - 1));
            int   lo = (int)cc;
            int   hi = (lo < W_ - 1) ? lo + 1 : lo;
            float f  = cc - (float)lo;
            xoff[2*s]   = lo;        xw[2*s]   = (1.0f - f) * v;
            xoff[2*s+1] = hi;        xw[2*s+1] = f * v;
        }
    }

    // ---- Channel loop: all address/weight math above is reused CG times ----
    const int c0 = cg * CG;
    const float* pbase = feat + ((size_t)b * C_ + c0) * (size_t)DHW_;
    float* obase = out + ((size_t)(r * C_ + c0)) * (size_t)NBINS + bin;

    for (int ci = 0; ci < CG; ci++) {
        const float* p = pbase + (size_t)ci * DHW_;
        float acc = 0.0f;

#pragma unroll
        for (int zt = 0; zt < NTAP; zt++) {
            const float* pz = p + zoff[zt];
            const float  wz = zw[zt];
#pragma unroll
            for (int yt = 0; yt < NTAP; yt++) {
                const float* py = pz + yoff[yt];
                const float  wzy = wz * yw[yt];
#pragma unroll
                for (int xt = 0; xt < NTAP; xt++) {
                    acc = fmaf(wzy * xw[xt], __ldg(py + xoff[xt]), acc);
                }
            }
        }

        obase[(size_t)ci * NBINS] = acc * 0.125f;   // mean over SN^3 = 8 samples
    }
}

extern "C" void kernel_launch(void* const* d_in, const int* in_sizes, int n_in,
                              void* d_out, int out_size)
{
    const float* feat = (const float*)d_in[0];
    const float* rois = (const float*)d_in[1];
    float* out = (float*)d_out;

    const int R = in_sizes[1] / 7;   // 256

    dim3 grid(R, C_ / CG, 1);        // 256 x 8 = 2048 blocks
    dim3 block(NBINS, 1, 1);         // 196 threads (7 warps)
    roialign3d_kernel<<<grid, block>>>(feat, rois, out, R);
}

// round 3
// speedup vs baseline: 4.7621x; 4.7621x over previous
#include <cuda_runtime.h>

// Problem constants (fixed by reference setup_inputs)
#define C_    128
#define D_    24
#define H_    128
#define W_    128
#define HW_   (H_ * W_)
#define DHW_  (D_ * HW_)
#define OUTH  7
#define OUTD  4
#define SN_   2
#define NBINS (OUTD * OUTH * OUTH)   // 196
#define CG    16                     // channels per block (gridDim.y = C_/CG = 8)

#define SCALE_XY 0.125f
#define SCALE_Z  0.25f

__global__ __launch_bounds__(NBINS, 4)
void roialign3d_kernel(const float* __restrict__ feat,
                       const float* __restrict__ rois,
                       float* __restrict__ out,
                       int R)
{
    const int r   = blockIdx.x;          // roi index
    const int cg  = blockIdx.y;          // channel group
    const int bin = threadIdx.x;         // 0..195  (output bin; contiguous out dim)
    const int w   = bin % OUTH;
    const int h   = (bin / OUTH) % OUTH;
    const int d   = bin / (OUTH * OUTH);

    // ---- ROI params (uniform across block) ----
    const float* roi = rois + (size_t)r * 7;
    const int   b  = (int)__ldg(roi + 0);
    const float x1 = __ldg(roi + 1) * SCALE_XY;
    const float y1 = __ldg(roi + 2) * SCALE_XY;
    const float x2 = __ldg(roi + 3) * SCALE_XY;
    const float y2 = __ldg(roi + 4) * SCALE_XY;
    const float z1 = __ldg(roi + 5) * SCALE_Z;
    const float z2 = __ldg(roi + 6) * SCALE_Z;

    const float bw = fmaxf(x2 - x1, 1.0f) * (1.0f / OUTH);
    const float bh = fmaxf(y2 - y1, 1.0f) * (1.0f / OUTH);
    const float bd = fmaxf(z2 - z1, 1.0f) * (1.0f / OUTD);

    // ---- Per-bin sample axis data (computed ONCE, reused for all channels) ----
    // Per axis-sample: base offset, step-to-high (0 if clipped), weights with
    // the validity flag folded in (indices are always clipped in-bounds, so
    // out-of-range samples simply contribute 0).
    int   zoff[SN_], zstep[SN_];
    float zw0[SN_], zw1[SN_];
    int   yoff[SN_], ystep[SN_];
    float yw0[SN_], yw1[SN_];
    int   xoff[SN_], xstep[SN_];
    float xw0[SN_], xw1[SN_];

#pragma unroll
    for (int s = 0; s < SN_; s++) {
        // z axis (dim D_)
        {
            float c  = z1 + ((float)d + 0.25f + 0.5f * (float)s) * bd;
            float v  = (c > -1.0f && c < (float)D_) ? 1.0f : 0.0f;
            float cc = fminf(fmaxf(c, 0.0f), (float)(D_ - 1));
            int   lo = (int)cc;                      // floor, cc >= 0
            float f  = cc - (float)lo;
            zoff[s]  = lo * HW_;
            zstep[s] = (lo < D_ - 1) ? HW_ : 0;
            zw0[s]   = (1.0f - f) * v;
            zw1[s]   = f * v;
        }
        // y axis (dim H_)
        {
            float c  = y1 + ((float)h + 0.25f + 0.5f * (float)s) * bh;
            float v  = (c > -1.0f && c < (float)H_) ? 1.0f : 0.0f;
            float cc = fminf(fmaxf(c, 0.0f), (float)(H_ - 1));
            int   lo = (int)cc;
            float f  = cc - (float)lo;
            yoff[s]  = lo * W_;
            ystep[s] = (lo < H_ - 1) ? W_ : 0;
            yw0[s]   = (1.0f - f) * v;
            yw1[s]   = f * v;
        }
        // x axis (dim W_)
        {
            float c  = x1 + ((float)w + 0.25f + 0.5f * (float)s) * bw;
            float v  = (c > -1.0f && c < (float)W_) ? 1.0f : 0.0f;
            float cc = fminf(fmaxf(c, 0.0f), (float)(W_ - 1));
            int   lo = (int)cc;
            float f  = cc - (float)lo;
            xoff[s]  = lo;
            xstep[s] = (lo < W_ - 1) ? 1 : 0;
            xw0[s]   = (1.0f - f) * v;
            xw1[s]   = f * v;
        }
    }

    // ---- Channel loop, 2 channels at a time (16 loads in flight) ----
    const int c0 = cg * CG;
    const float* pbase = feat + ((size_t)b * C_ + c0) * (size_t)DHW_;
    float* obase = out + ((size_t)(r * C_ + c0)) * (size_t)NBINS + bin;

    for (int ci = 0; ci < CG; ci += 2) {
        const float* pA = pbase + (size_t)ci * DHW_;
        const float* pB = pA + DHW_;
        float accA = 0.0f;
        float accB = 0.0f;

#pragma unroll
        for (int sz = 0; sz < SN_; sz++) {
            const int oz = zoff[sz];
            const int dz = zstep[sz];
#pragma unroll
            for (int sy = 0; sy < SN_; sy++) {
                const int oy = yoff[sy];
                const int dy = ystep[sy];
#pragma unroll
                for (int sx = 0; sx < SN_; sx++) {
                    const int base = oz + oy + xoff[sx];
                    const int dx   = xstep[sx];
                    const float* qA = pA + base;
                    const float* qB = pB + base;

                    float a000 = __ldg(qA);
                    float a001 = __ldg(qA + dx);
                    float a010 = __ldg(qA + dy);
                    float a011 = __ldg(qA + dy + dx);
                    float a100 = __ldg(qA + dz);
                    float a101 = __ldg(qA + dz + dx);
                    float a110 = __ldg(qA + dz + dy);
                    float a111 = __ldg(qA + dz + dy + dx);

                    float b000 = __ldg(qB);
                    float b001 = __ldg(qB + dx);
                    float b010 = __ldg(qB + dy);
                    float b011 = __ldg(qB + dy + dx);
                    float b100 = __ldg(qB + dz);
                    float b101 = __ldg(qB + dz + dx);
                    float b110 = __ldg(qB + dz + dy);
                    float b111 = __ldg(qB + dz + dy + dx);

                    float wx0 = xw0[sx], wx1 = xw1[sx];
                    float wy0 = yw0[sy], wy1 = yw1[sy];
                    float wz0 = zw0[sz], wz1 = zw1[sz];

                    float tA0 = fmaf(wx1, a001, wx0 * a000);
                    float tA1 = fmaf(wx1, a011, wx0 * a010);
                    float tA2 = fmaf(wx1, a101, wx0 * a100);
                    float tA3 = fmaf(wx1, a111, wx0 * a110);
                    float uA0 = fmaf(wy1, tA1, wy0 * tA0);
                    float uA1 = fmaf(wy1, tA3, wy0 * tA2);
                    accA = fmaf(wz1, uA1, fmaf(wz0, uA0, accA));

                    float tB0 = fmaf(wx1, b001, wx0 * b000);
                    float tB1 = fmaf(wx1, b011, wx0 * b010);
                    float tB2 = fmaf(wx1, b101, wx0 * b100);
                    float tB3 = fmaf(wx1, b111, wx0 * b110);
                    float uB0 = fmaf(wy1, tB1, wy0 * tB0);
                    float uB1 = fmaf(wy1, tB3, wy0 * tB2);
                    accB = fmaf(wz1, uB1, fmaf(wz0, uB0, accB));
                }
            }
        }

        obase[(size_t)ci * NBINS]       = accA * 0.125f;  // mean over SN^3 = 8
        obase[(size_t)(ci + 1) * NBINS] = accB * 0.125f;
    }
}

extern "C" void kernel_launch(void* const* d_in, const int* in_sizes, int n_in,
                              void* d_out, int out_size)
{
    const float* feat = (const float*)d_in[0];
    const float* rois = (const float*)d_in[1];
    float* out = (float*)d_out;

    const int R = in_sizes[1] / 7;   // 256

    dim3 grid(R, C_ / CG, 1);        // 256 x 8 = 2048 blocks
    dim3 block(NBINS, 1, 1);         // 196 threads (7 warps)
    roialign3d_kernel<<<grid, block>>>(feat, rois, out, R);
}

// round 4
// speedup vs baseline: 4.7821x; 1.0042x over previous
#include <cuda_runtime.h>

// Problem constants (fixed by reference setup_inputs)
#define C_    128
#define D_    24
#define H_    128
#define W_    128
#define HW_   (H_ * W_)
#define DHW_  (D_ * HW_)
#define OUTH  7
#define OUTD  4
#define SN_   2
#define NBINS (OUTD * OUTH * OUTH)   // 196
#define CG    16                     // channels per block (gridDim.y = C_/CG = 8)

#define SCALE_XY 0.125f
#define SCALE_Z  0.25f

__global__ __launch_bounds__(NBINS, 3)
void roialign3d_kernel(const float* __restrict__ feat,
                       const float* __restrict__ rois,
                       float* __restrict__ out,
                       int R)
{
    const int r   = blockIdx.x;          // roi index
    const int cg  = blockIdx.y;          // channel group
    const int bin = threadIdx.x;         // 0..195  (output bin; contiguous out dim)
    const int w   = bin % OUTH;
    const int h   = (bin / OUTH) % OUTH;
    const int d   = bin / (OUTH * OUTH);

    // ---- ROI params (uniform across block) ----
    const float* roi = rois + (size_t)r * 7;
    const int   b  = (int)__ldg(roi + 0);
    const float x1 = __ldg(roi + 1) * SCALE_XY;
    const float y1 = __ldg(roi + 2) * SCALE_XY;
    const float x2 = __ldg(roi + 3) * SCALE_XY;
    const float y2 = __ldg(roi + 4) * SCALE_XY;
    const float z1 = __ldg(roi + 5) * SCALE_Z;
    const float z2 = __ldg(roi + 6) * SCALE_Z;

    const float bw = fmaxf(x2 - x1, 1.0f) * (1.0f / OUTH);
    const float bh = fmaxf(y2 - y1, 1.0f) * (1.0f / OUTH);
    const float bd = fmaxf(z2 - z1, 1.0f) * (1.0f / OUTD);

    // ---- Per-bin sample axis data (computed ONCE, reused for all channels) ----
    int   zoff[SN_], zstep[SN_];
    float zw0[SN_], zw1[SN_];
    int   yoff[SN_], ystep[SN_];
    float yw0[SN_], yw1[SN_];
    int   xoff[SN_], xstep[SN_];
    float xw0[SN_], xw1[SN_];

#pragma unroll
    for (int s = 0; s < SN_; s++) {
        // z axis (dim D_)
        {
            float c  = z1 + ((float)d + 0.25f + 0.5f * (float)s) * bd;
            float v  = (c > -1.0f && c < (float)D_) ? 1.0f : 0.0f;
            float cc = fminf(fmaxf(c, 0.0f), (float)(D_ - 1));
            int   lo = (int)cc;                      // floor, cc >= 0
            float f  = cc - (float)lo;
            zoff[s]  = lo * HW_;
            zstep[s] = (lo < D_ - 1) ? HW_ : 0;
            zw0[s]   = (1.0f - f) * v;
            zw1[s]   = f * v;
        }
        // y axis (dim H_)
        {
            float c  = y1 + ((float)h + 0.25f + 0.5f * (float)s) * bh;
            float v  = (c > -1.0f && c < (float)H_) ? 1.0f : 0.0f;
            float cc = fminf(fmaxf(c, 0.0f), (float)(H_ - 1));
            int   lo = (int)cc;
            float f  = cc - (float)lo;
            yoff[s]  = lo * W_;
            ystep[s] = (lo < H_ - 1) ? W_ : 0;
            yw0[s]   = (1.0f - f) * v;
            yw1[s]   = f * v;
        }
        // x axis (dim W_)
        {
            float c  = x1 + ((float)w + 0.25f + 0.5f * (float)s) * bw;
            float v  = (c > -1.0f && c < (float)W_) ? 1.0f : 0.0f;
            float cc = fminf(fmaxf(c, 0.0f), (float)(W_ - 1));
            int   lo = (int)cc;
            float f  = cc - (float)lo;
            xoff[s]  = lo;
            xstep[s] = (lo < W_ - 1) ? 1 : 0;
            xw0[s]   = (1.0f - f) * v;
            xw1[s]   = f * v;
        }
    }

    // ---- Channel loop, 4 channels at a time (32 loads in flight) ----
    const int c0 = cg * CG;
    const float* pbase = feat + ((size_t)b * C_ + c0) * (size_t)DHW_;
    float* obase = out + ((size_t)(r * C_ + c0)) * (size_t)NBINS + bin;

    for (int ci = 0; ci < CG; ci += 4) {
        const float* pA = pbase + (size_t)ci * DHW_;
        const float* pB = pA + DHW_;
        const float* pC = pB + DHW_;
        const float* pD = pC + DHW_;
        float accA = 0.0f, accB = 0.0f, accC = 0.0f, accD = 0.0f;

#pragma unroll
        for (int sz = 0; sz < SN_; sz++) {
            const int oz = zoff[sz];
            const int dz = zstep[sz];
#pragma unroll
            for (int sy = 0; sy < SN_; sy++) {
                const int oy = yoff[sy];
                const int dy = ystep[sy];
#pragma unroll
                for (int sx = 0; sx < SN_; sx++) {
                    // 8 corner offsets shared by all 4 channels
                    const int o0 = oz + oy + xoff[sx];
                    const int o1 = o0 + xstep[sx];
                    const int o2 = o0 + dy;
                    const int o3 = o2 + xstep[sx];
                    const int o4 = o0 + dz;
                    const int o5 = o4 + xstep[sx];
                    const int o6 = o4 + dy;
                    const int o7 = o6 + xstep[sx];

                    float a0 = __ldg(pA + o0), a1 = __ldg(pA + o1);
                    float a2 = __ldg(pA + o2), a3 = __ldg(pA + o3);
                    float a4 = __ldg(pA + o4), a5 = __ldg(pA + o5);
                    float a6 = __ldg(pA + o6), a7 = __ldg(pA + o7);

                    float b0 = __ldg(pB + o0), b1 = __ldg(pB + o1);
                    float b2 = __ldg(pB + o2), b3 = __ldg(pB + o3);
                    float b4 = __ldg(pB + o4), b5 = __ldg(pB + o5);
                    float b6 = __ldg(pB + o6), b7 = __ldg(pB + o7);

                    float c0v = __ldg(pC + o0), c1v = __ldg(pC + o1);
                    float c2v = __ldg(pC + o2), c3v = __ldg(pC + o3);
                    float c4v = __ldg(pC + o4), c5v = __ldg(pC + o5);
                    float c6v = __ldg(pC + o6), c7v = __ldg(pC + o7);

                    float d0v = __ldg(pD + o0), d1v = __ldg(pD + o1);
                    float d2v = __ldg(pD + o2), d3v = __ldg(pD + o3);
                    float d4v = __ldg(pD + o4), d5v = __ldg(pD + o5);
                    float d6v = __ldg(pD + o6), d7v = __ldg(pD + o7);

                    const float wx0 = xw0[sx], wx1 = xw1[sx];
                    const float wy0 = yw0[sy], wy1 = yw1[sy];
                    const float wz0 = zw0[sz], wz1 = zw1[sz];

                    {
                        float t0 = fmaf(wx1, a1, wx0 * a0);
                        float t1 = fmaf(wx1, a3, wx0 * a2);
                        float t2 = fmaf(wx1, a5, wx0 * a4);
                        float t3 = fmaf(wx1, a7, wx0 * a6);
                        float u0 = fmaf(wy1, t1, wy0 * t0);
                        float u1 = fmaf(wy1, t3, wy0 * t2);
                        accA = fmaf(wz1, u1, fmaf(wz0, u0, accA));
                    }
                    {
                        float t0 = fmaf(wx1, b1, wx0 * b0);
                        float t1 = fmaf(wx1, b3, wx0 * b2);
                        float t2 = fmaf(wx1, b5, wx0 * b4);
                        float t3 = fmaf(wx1, b7, wx0 * b6);
                        float u0 = fmaf(wy1, t1, wy0 * t0);
                        float u1 = fmaf(wy1, t3, wy0 * t2);
                        accB = fmaf(wz1, u1, fmaf(wz0, u0, accB));
                    }
                    {
                        float t0 = fmaf(wx1, c1v, wx0 * c0v);
                        float t1 = fmaf(wx1, c3v, wx0 * c2v);
                        float t2 = fmaf(wx1, c5v, wx0 * c4v);
                        float t3 = fmaf(wx1, c7v, wx0 * c6v);
                        float u0 = fmaf(wy1, t1, wy0 * t0);
                        float u1 = fmaf(wy1, t3, wy0 * t2);
                        accC = fmaf(wz1, u1, fmaf(wz0, u0, accC));
                    }
                    {
                        float t0 = fmaf(wx1, d1v, wx0 * d0v);
                        float t1 = fmaf(wx1, d3v, wx0 * d2v);
                        float t2 = fmaf(wx1, d5v, wx0 * d4v);
                        float t3 = fmaf(wx1, d7v, wx0 * d6v);
                        float u0 = fmaf(wy1, t1, wy0 * t0);
                        float u1 = fmaf(wy1, t3, wy0 * t2);
                        accD = fmaf(wz1, u1, fmaf(wz0, u0, accD));
                    }
                }
            }
        }

        obase[(size_t)ci * NBINS]       = accA * 0.125f;  // mean over SN^3 = 8
        obase[(size_t)(ci + 1) * NBINS] = accB * 0.125f;
        obase[(size_t)(ci + 2) * NBINS] = accC * 0.125f;
        obase[(size_t)(ci + 3) * NBINS] = accD * 0.125f;
    }
}

extern "C" void kernel_launch(void* const* d_in, const int* in_sizes, int n_in,
                              void* d_out, int out_size)
{
    const float* feat = (const float*)d_in[0];
    const float* rois = (const float*)d_in[1];
    float* out = (float*)d_out;

    const int R = in_sizes[1] / 7;   // 256

    dim3 grid(R, C_ / CG, 1);        // 256 x 8 = 2048 blocks
    dim3 block(NBINS, 1, 1);         // 196 threads (7 warps)
    roialign3d_kernel<<<grid, block>>>(feat, rois, out, R);
}

// round 5
// speedup vs baseline: 8.4588x; 1.7688x over previous
#include <cuda_runtime.h>

// Problem constants (fixed by reference setup_inputs)
#define C_    128
#define D_    24
#define H_    128
#define W_    128
#define HW_   (H_ * W_)
#define DHW_  (D_ * HW_)
#define OUTH  7
#define OUTD  4
#define SN_   2
#define NBINS (OUTD * OUTH * OUTH)   // 196
#define CG    16                     // channels per block (gridDim.y = 8)
#define TPB   224                    // 7 warps; warp w-index = bin-row h

#define SCALE_XY 0.125f
#define SCALE_Z  0.25f

__global__ __launch_bounds__(TPB, 3)
void roialign3d_kernel(const float* __restrict__ feat,
                       const float* __restrict__ rois,
                       float* __restrict__ out,
                       int R)
{
    const int r    = blockIdx.x;         // roi
    const int cg   = blockIdx.y;         // channel group
    const int tid  = threadIdx.x;
    const int h    = tid >> 5;           // warp id = output h (0..6)
    const int lane = tid & 31;
    // lane -> (w bin, x tap). 28 active lanes; lanes 28..31 mirror w=6 (weight 0).
    const int  wbin   = (lane >> 2) < OUTH ? (lane >> 2) : (OUTH - 1);
    const int  tap    = lane & 3;        // (sample = tap>>1, corner = tap&1)
    const bool active = (lane >> 2) < OUTH;

    // ---- ROI params (uniform) ----
    const float* roi = rois + (size_t)r * 7;
    const int   b  = (int)__ldg(roi + 0);
    const float x1 = __ldg(roi + 1) * SCALE_XY;
    const float y1 = __ldg(roi + 2) * SCALE_XY;
    const float x2 = __ldg(roi + 3) * SCALE_XY;
    const float y2 = __ldg(roi + 4) * SCALE_XY;
    const float z1 = __ldg(roi + 5) * SCALE_Z;
    const float z2 = __ldg(roi + 6) * SCALE_Z;

    const float bw = fmaxf(x2 - x1, 1.0f) * (1.0f / OUTH);
    const float bh = fmaxf(y2 - y1, 1.0f) * (1.0f / OUTH);
    const float bd = fmaxf(z2 - z1, 1.0f) * (1.0f / OUTD);

    // ---- This lane's x tap: offset (clipped in-bounds) + weight (validity folded) ----
    int   xoff;
    float xw;
    {
        const int   s  = tap >> 1;
        float c  = x1 + ((float)wbin + 0.25f + 0.5f * (float)s) * bw;
        float v  = (c > -1.0f && c < (float)W_) ? 1.0f : 0.0f;
        float cc = fminf(fmaxf(c, 0.0f), (float)(W_ - 1));
        int   lo = (int)cc;
        int   hi = (lo < W_ - 1) ? lo + 1 : lo;
        float f  = cc - (float)lo;
        xoff = (tap & 1) ? hi : lo;
        xw   = ((tap & 1) ? f : (1.0f - f)) * v;
        if (!active) xw = 0.0f;
    }

    // ---- 4 y taps for this warp's h (uniform across warp) ----
    int   yoff[4];
    float yw[4];
#pragma unroll
    for (int s = 0; s < SN_; s++) {
        float c  = y1 + ((float)h + 0.25f + 0.5f * (float)s) * bh;
        float v  = (c > -1.0f && c < (float)H_) ? 1.0f : 0.0f;
        float cc = fminf(fmaxf(c, 0.0f), (float)(H_ - 1));
        int   lo = (int)cc;
        int   hi = (lo < H_ - 1) ? lo + 1 : lo;
        float f  = cc - (float)lo;
        yoff[2*s]   = lo * W_;  yw[2*s]   = (1.0f - f) * v;
        yoff[2*s+1] = hi * W_;  yw[2*s+1] = f * v;
    }

    const int c0 = cg * CG;
    const float* pbase = feat + ((size_t)b * C_ + c0) * (size_t)DHW_ + xoff;
    float* obase = out + ((size_t)(r * C_ + c0)) * (size_t)NBINS + h * OUTH + wbin;

    // ---- Loop over d bin-rows ----
    for (int d = 0; d < OUTD; d++) {
        // 4 z taps
        int   zoff[4];
        float zw[4];
#pragma unroll
        for (int s = 0; s < SN_; s++) {
            float c  = z1 + ((float)d + 0.25f + 0.5f * (float)s) * bd;
            float v  = (c > -1.0f && c < (float)D_) ? 1.0f : 0.0f;
            float cc = fminf(fmaxf(c, 0.0f), (float)(D_ - 1));
            int   lo = (int)cc;
            int   hi = (lo < D_ - 1) ? lo + 1 : lo;
            float f  = cc - (float)lo;
            zoff[2*s]   = lo * HW_;  zw[2*s]   = (1.0f - f) * v;
            zoff[2*s+1] = hi * HW_;  zw[2*s+1] = f * v;
        }

        // 16 row offsets + scalar weights (uniform across warp)
        int   rowoff[16];
        float wzy[16];
#pragma unroll
        for (int zt = 0; zt < 4; zt++)
#pragma unroll
            for (int yt = 0; yt < 4; yt++) {
                rowoff[zt * 4 + yt] = zoff[zt] + yoff[yt];
                wzy[zt * 4 + yt]    = zw[zt] * yw[yt];
            }

        float* od = obase + (size_t)d * (OUTH * OUTH);

        // ---- Channel loop, 2 channels at a time (32 independent LDGs) ----
        for (int ci = 0; ci < CG; ci += 2) {
            const float* pA = pbase + (size_t)ci * DHW_;
            const float* pB = pA + DHW_;

            float vA[16], vB[16];
#pragma unroll
            for (int i = 0; i < 16; i++) {
                vA[i] = __ldg(pA + rowoff[i]);
                vB[i] = __ldg(pB + rowoff[i]);
            }

            // two partial chains each to shorten the FMA dependency
            float a0 = 0.f, a1 = 0.f, b0 = 0.f, b1 = 0.f;
#pragma unroll
            for (int i = 0; i < 16; i += 2) {
                a0 = fmaf(wzy[i],     vA[i],     a0);
                a1 = fmaf(wzy[i + 1], vA[i + 1], a1);
                b0 = fmaf(wzy[i],     vB[i],     b0);
                b1 = fmaf(wzy[i + 1], vB[i + 1], b1);
            }
            float accA = (a0 + a1) * xw;
            float accB = (b0 + b1) * xw;

            // reduce across the 4 x-taps (lanes 4w..4w+3)
            accA += __shfl_xor_sync(0xFFFFFFFFu, accA, 1);
            accA += __shfl_xor_sync(0xFFFFFFFFu, accA, 2);
            accB += __shfl_xor_sync(0xFFFFFFFFu, accB, 1);
            accB += __shfl_xor_sync(0xFFFFFFFFu, accB, 2);

            if (active && tap == 0) {
                od[(size_t)ci * NBINS]       = accA * 0.125f;  // mean over 8 samples
                od[(size_t)(ci + 1) * NBINS] = accB * 0.125f;
            }
        }
    }
}

extern "C" void kernel_launch(void* const* d_in, const int* in_sizes, int n_in,
                              void* d_out, int out_size)
{
    const float* feat = (const float*)d_in[0];
    const float* rois = (const float*)d_in[1];
    float* out = (float*)d_out;

    const int R = in_sizes[1] / 7;   // 256

    dim3 grid(R, C_ / CG, 1);        // 256 x 8 = 2048 blocks
    dim3 block(TPB, 1, 1);           // 224 threads (7 warps)
    roialign3d_kernel<<<grid, block>>>(feat, rois, out, R);
}